// round 13
// baseline (speedup 1.0000x reference)
#include <cuda_runtime.h>
#include <cstdint>

// FlexGroupedVarPatchEmbed, single-kernel tf32 GEMM, tuned for occupancy.
// out[b,v,l,e] = sum_k x_patch[m,k] * W[var,e,k] + bias[var,e]
// CTA: N=128 E-cols, 8 M-subtiles of 64 rows (one patch row each), A tiles
// double-buffered via cp.async (16KB each), B tile (32KB) loaded once with
// RNA-rounded tf32 (LDG+cvt+STS). smem 64KB, <=84 regs -> 3 CTAs/SM.
// mma.sync.m16n8k8.tf32, RNA rounding on both operands (~4e-4 norm err).

#define NTHREADS 256

__device__ __forceinline__ uint32_t smem_u32(const void* p) {
    uint32_t a;
    asm("{ .reg .u64 t; cvta.to.shared.u64 t, %1; cvt.u32.u64 %0, t; }" : "=r"(a) : "l"(p));
    return a;
}
__device__ __forceinline__ uint32_t sw128(uint32_t off) { return off ^ ((off >> 3) & 0x70); }

__device__ __forceinline__ void cp16(uint32_t dst, const void* src) {
    asm volatile("cp.async.cg.shared.global [%0], [%1], 16;" :: "r"(dst), "l"(src));
}
#define CP_COMMIT() asm volatile("cp.async.commit_group;" ::: "memory")
#define CP_WAIT(n)  asm volatile("cp.async.wait_group %0;" :: "n"(n) : "memory")

__device__ __forceinline__ void ldmx4(uint32_t* f, uint32_t addr) {
    asm volatile("ldmatrix.sync.aligned.m8n8.x4.shared.b16 {%0,%1,%2,%3}, [%4];"
                 : "=r"(f[0]), "=r"(f[1]), "=r"(f[2]), "=r"(f[3]) : "r"(addr));
}
__device__ __forceinline__ void mma_tf32(float* c, const uint32_t* a, uint32_t b0, uint32_t b1) {
    asm volatile(
        "mma.sync.aligned.m16n8k8.row.col.f32.tf32.tf32.f32 "
        "{%0,%1,%2,%3}, {%4,%5,%6,%7}, {%8,%9}, {%0,%1,%2,%3};"
        : "+f"(c[0]), "+f"(c[1]), "+f"(c[2]), "+f"(c[3])
        : "r"(a[0]), "r"(a[1]), "r"(a[2]), "r"(a[3]), "r"(b0), "r"(b1));
}
__device__ __forceinline__ uint32_t rna(float f) {
    uint32_t r;
    asm("cvt.rna.tf32.f32 %0, %1;" : "=r"(r) : "f"(f));
    return r;
}

// smem: B 32KB (two 16KB k-halves, 128 rows x 128B) |
//       A buf0 16KB | A buf1 16KB (each: two 8KB k-halves, 64 rows x 128B)
#define OFF_B   0
#define OFF_A0  32768
#define SMEM_SZ 65536

__global__ __launch_bounds__(NTHREADS, 3)
void gemm(const float* __restrict__ x,
          const int* __restrict__ vars,
          const float* __restrict__ pw,
          const float* __restrict__ pb,
          float* __restrict__ out) {
    extern __shared__ char smem[];
    const uint32_t sb = smem_u32(smem);
    const int tid  = threadIdx.x;
    const int lane = tid & 31;
    const int wid  = tid >> 5;

    const int e0  = blockIdx.x << 7;    // 128 E-cols
    const int hh0 = blockIdx.y << 3;    // 8 patch rows (M-subtiles of 64)
    const int bv  = blockIdx.z;
    const int v   = bv & 15;
    const int var = vars[v];

    const float* xb = x + (size_t)bv * (512u * 512u);

    // ---- A subtile loader: one patch row (x rows hh*8..hh*8+7), m=ww ----
    // chunk idx: m = idx>>4 (0..63), c = idx&15: p = c>>1, h = c&1
    #define LOAD_A(bufbyte, hh) do {                                              \
        const float* _xr = xb + (size_t)(hh) * (8u * 512u);                       \
        _Pragma("unroll")                                                         \
        for (int _j = 0; _j < 4; _j++) {                                          \
            int _idx = tid + _j * 256;                                            \
            int _m = _idx >> 4, _p = (_idx >> 1) & 7, _h = _idx & 1;              \
            const float* _s = _xr + (size_t)_p * 512u + (_m << 3) + (_h << 2);    \
            uint32_t _d = sb + (bufbyte) + (uint32_t)((_p >> 2) << 13)            \
                        + sw128((uint32_t)(_m * 128 + (_p & 3) * 32 + _h * 16));  \
            cp16(_d, _s);                                                         \
        }                                                                         \
    } while (0)

    LOAD_A(OFF_A0, hh0);
    CP_COMMIT();                        // G0: A0

    // ---- B tile: gather W[var], RNA-round to tf32, STS (one-time) ----
    {
        const float* wb = pw + ((size_t)var * 1024u + e0) * 64u;
        #pragma unroll
        for (int j = 0; j < 8; j++) {
            int idx = tid + j * 256;        // n*16 + c
            int n  = idx >> 4;
            int c  = idx & 15;
            int kh = c >> 3, cc = c & 7;
            float4 w = *(const float4*)(wb + (size_t)n * 64u + kh * 32 + cc * 4);
            uint4 t;
            t.x = rna(w.x); t.y = rna(w.y); t.z = rna(w.z); t.w = rna(w.w);
            uint32_t d = sb + OFF_B + (uint32_t)(kh << 14)
                       + sw128((uint32_t)(n * 128 + cc * 16));
            *(uint4*)(smem + (d - sb)) = t;
        }
    }

    LOAD_A(OFF_A0 + 16384, hh0 + 1);
    CP_COMMIT();                        // G1: A1

    // ---- warp layout & bias ----
    const int wm = (wid & 1) << 5;      // 0 / 32 (within m64)
    const int wn = (wid >> 1) << 5;     // 0,32,64,96
    const int c0 = wn + ((lane & 3) << 1);
    float bx[4], by[4];
    {
        const float* bias = pb + (size_t)var * 1024u + e0;
        #pragma unroll
        for (int nt = 0; nt < 4; nt++) {
            bx[nt] = bias[c0 + nt * 8];
            by[nt] = bias[c0 + nt * 8 + 1];
        }
    }

    const uint32_t a_row = wm + (lane & 15);
    const uint32_t a_kb  = (lane >> 4) << 4;
    const uint32_t b_row = wn + (lane & 7) + ((lane >> 4) << 3);
    const uint32_t b_kb  = ((lane >> 3) & 1) << 4;
    const int r0 = wm + (lane >> 2);

    CP_WAIT(1);                         // A0 done (A1 may be in flight)
    __syncthreads();                    // A0 + B visible

    #pragma unroll 1
    for (int s = 0; s < 8; s++) {
        const uint32_t abase = sb + OFF_A0 + ((s & 1) << 14);
        float* obase = out + ((size_t)bv * 4096u + (size_t)(hh0 + s) * 64u) * 1024u + e0;

        float acc[2][4][4];
        #pragma unroll
        for (int mt = 0; mt < 2; mt++)
            #pragma unroll
            for (int nt = 0; nt < 4; nt++)
                #pragma unroll
                for (int jj = 0; jj < 4; jj++) acc[mt][nt][jj] = 0.f;

        #pragma unroll
        for (int ks = 0; ks < 8; ks++) {
            const uint32_t kbyte = (uint32_t)((ks & 3) * 32);
            // B fragments for this k-step (n32 = 2 ldmx4)
            uint32_t bf[2][4];
            {
                uint32_t hbase = sb + OFF_B + (uint32_t)((ks >> 2) << 14);
                #pragma unroll
                for (int nt2 = 0; nt2 < 2; nt2++)
                    ldmx4(bf[nt2], hbase + sw128((b_row + nt2 * 16) * 128 + b_kb + kbyte));
            }
            // A fragments for both m16 subtiles, RNA-rounded
            uint32_t af[2][4];
            {
                uint32_t hbase = abase + (uint32_t)((ks >> 2) << 13);
                #pragma unroll
                for (int mt = 0; mt < 2; mt++) {
                    ldmx4(af[mt], hbase + sw128((a_row + mt * 16) * 128 + a_kb + kbyte));
                    #pragma unroll
                    for (int jj = 0; jj < 4; jj++)
                        af[mt][jj] = rna(__uint_as_float(af[mt][jj]));
                }
            }
            #pragma unroll
            for (int mt = 0; mt < 2; mt++)
                #pragma unroll
                for (int nt = 0; nt < 4; nt++)
                    mma_tf32(acc[mt][nt], af[mt],
                             bf[nt >> 1][(nt & 1) * 2],
                             bf[nt >> 1][(nt & 1) * 2 + 1]);
        }

        // ---- epilogue: bias + stores (quad-contiguous 32B sectors) ----
        #pragma unroll
        for (int mt = 0; mt < 2; mt++) {
            int row = r0 + mt * 16;
            #pragma unroll
            for (int nt = 0; nt < 4; nt++) {
                int col = c0 + nt * 8;
                float2 v0 = make_float2(acc[mt][nt][0] + bx[nt], acc[mt][nt][1] + by[nt]);
                float2 v1 = make_float2(acc[mt][nt][2] + bx[nt], acc[mt][nt][3] + by[nt]);
                *(float2*)(obase + (size_t)row * 1024u + col) = v0;
                *(float2*)(obase + (size_t)(row + 8) * 1024u + col) = v1;
            }
        }

        __syncthreads();                // all warps done reading buf(s&1)
        if (s + 2 < 8) {
            LOAD_A(OFF_A0 + ((s & 1) << 14), hh0 + s + 2);
            CP_COMMIT();
        }
        if (s + 1 < 8) {
            if (s + 2 < 8) { CP_WAIT(1); } else { CP_WAIT(0); }
            __syncthreads();            // A(s+1) visible
        }
    }
    #undef LOAD_A
}

extern "C" void kernel_launch(void* const* d_in, const int* in_sizes, int n_in,
                              void* d_out, int out_size) {
    const float* x    = (const float*)d_in[0];
    const int*   vars = (const int*)d_in[1];
    const float* pw   = (const float*)d_in[2];
    const float* pb   = (const float*)d_in[3];
    float*       out  = (float*)d_out;

    cudaFuncSetAttribute(gemm, cudaFuncAttributeMaxDynamicSharedMemorySize, SMEM_SZ);
    gemm<<<dim3(8, 8, 32), NTHREADS, SMEM_SZ>>>(x, vars, pw, pb, out);
}

// round 14
// speedup vs baseline: 1.1607x; 1.1607x over previous
#include <cuda_runtime.h>
#include <cstdint>

// FlexGroupedVarPatchEmbed, single-kernel tf32 GEMM.
// out[b,v,l,e] = sum_k x_patch[m,k] * W[var,e,k] + bias[var,e]
// R12 structure (M=128 x N=128 tile, HPG=4 M-tiles, B frags hoisted to regs,
// 2 CTAs/SM) + pipelined A-fragment LDSM (unroll-2 ks with prefetch),
// RNA-rounded B at load, bit-trick (+0x1000) rounding on A fragments.

#define NTHREADS 256
#define HPG 4

__device__ __forceinline__ uint32_t smem_u32(const void* p) {
    uint32_t a;
    asm("{ .reg .u64 t; cvta.to.shared.u64 t, %1; cvt.u32.u64 %0, t; }" : "=r"(a) : "l"(p));
    return a;
}
__device__ __forceinline__ uint32_t sw128(uint32_t off) { return off ^ ((off >> 3) & 0x70); }

__device__ __forceinline__ void cp16(uint32_t dst, const void* src) {
    asm volatile("cp.async.cg.shared.global [%0], [%1], 16;" :: "r"(dst), "l"(src));
}
#define CP_COMMIT() asm volatile("cp.async.commit_group;" ::: "memory")
#define CP_WAIT(n)  asm volatile("cp.async.wait_group %0;" :: "n"(n) : "memory")

__device__ __forceinline__ void ldmx4(uint32_t* f, uint32_t addr) {
    asm volatile("ldmatrix.sync.aligned.m8n8.x4.shared.b16 {%0,%1,%2,%3}, [%4];"
                 : "=r"(f[0]), "=r"(f[1]), "=r"(f[2]), "=r"(f[3]) : "r"(addr));
}
__device__ __forceinline__ void mma_tf32(float* c, const uint32_t* a, uint32_t b0, uint32_t b1) {
    asm volatile(
        "mma.sync.aligned.m16n8k8.row.col.f32.tf32.tf32.f32 "
        "{%0,%1,%2,%3}, {%4,%5,%6,%7}, {%8,%9}, {%0,%1,%2,%3};"
        : "+f"(c[0]), "+f"(c[1]), "+f"(c[2]), "+f"(c[3])
        : "r"(a[0]), "r"(a[1]), "r"(a[2]), "r"(a[3]), "r"(b0), "r"(b1));
}
__device__ __forceinline__ uint32_t rna(float f) {
    uint32_t r;
    asm("cvt.rna.tf32.f32 %0, %1;" : "=r"(r) : "f"(f));
    return r;
}
// round-half-up at the tf32 truncation boundary (HW drops low 13 bits)
__device__ __forceinline__ void round4(uint32_t* a) {
    a[0] += 0x1000u; a[1] += 0x1000u; a[2] += 0x1000u; a[3] += 0x1000u;
}

// smem: B tile 32KB (two 16KB k-halves, 128 rows x 128B) | A buf0 32KB | A buf1 32KB
#define OFF_B  0
#define OFF_A0 32768
#define SMEM_SZ 98304

__global__ __launch_bounds__(NTHREADS, 2)
void gemm(const float* __restrict__ x,
          const int* __restrict__ vars,
          const float* __restrict__ pw,
          const float* __restrict__ pb,
          float* __restrict__ out) {
    extern __shared__ char smem[];
    const uint32_t sb = smem_u32(smem);
    const int tid  = threadIdx.x;
    const int lane = tid & 31;
    const int wid  = tid >> 5;

    const int e0  = blockIdx.x << 7;
    const int hp0 = blockIdx.y * HPG;
    const int bv  = blockIdx.z;
    const int v   = bv & 15;
    const int var = vars[v];

    const float* xb = x + (size_t)bv * (512u * 512u);

    // ---- A tile loader: patchify x directly (2048 cp16) ----
    #define LOAD_A(bufbyte, hp) do {                                              \
        const float* _xr = xb + (size_t)(hp) * (16u * 512u);                      \
        _Pragma("unroll")                                                         \
        for (int _j = 0; _j < 8; _j++) {                                          \
            int _idx = tid + _j * 256;                                            \
            int _m = _idx >> 4, _p = (_idx >> 1) & 7, _h = _idx & 1;              \
            const float* _s = _xr + (size_t)(((_m >> 6) << 3) + _p) * 512u        \
                              + ((_m & 63) << 3) + (_h << 2);                     \
            uint32_t _d = sb + (bufbyte) + (uint32_t)((_p >> 2) << 14)            \
                        + sw128((uint32_t)(_m * 128 + (_p & 3) * 32 + _h * 16));  \
            cp16(_d, _s);                                                         \
        }                                                                         \
    } while (0)

    LOAD_A(OFF_A0, hp0);
    CP_COMMIT();                        // G0: A0

    // ---- B tile: gather W[var], RNA-round, STS (one-time, sync) ----
    {
        const float* wb = pw + ((size_t)var * 1024u + e0) * 64u;
        #pragma unroll
        for (int j = 0; j < 8; j++) {
            int idx = tid + j * 256;        // n*16 + c
            int n  = idx >> 4;
            int c  = idx & 15;
            int kh = c >> 3, cc = c & 7;
            float4 w = *(const float4*)(wb + (size_t)n * 64u + kh * 32 + cc * 4);
            uint4 t;
            t.x = rna(w.x); t.y = rna(w.y); t.z = rna(w.z); t.w = rna(w.w);
            uint32_t off = (uint32_t)(kh << 14) + sw128((uint32_t)(n * 128 + cc * 16));
            *(uint4*)(smem + OFF_B + off) = t;
        }
    }

    LOAD_A(OFF_A0 + 32768, hp0 + 1);
    CP_COMMIT();                        // G1: A1

    // ---- warp layout & bias ----
    const int wm = (wid & 1) << 6;
    const int wn = (wid >> 1) << 5;
    const int c0 = wn + ((lane & 3) << 1);
    float bx[4], by[4];
    {
        const float* bias = pb + (size_t)var * 1024u + e0;
        #pragma unroll
        for (int nt = 0; nt < 4; nt++) {
            bx[nt] = bias[c0 + nt * 8];
            by[nt] = bias[c0 + nt * 8 + 1];
        }
    }

    const uint32_t a_row = wm + (lane & 15);
    const uint32_t a_kb  = (lane >> 4) << 4;
    const uint32_t b_row = wn + (lane & 7) + ((lane >> 4) << 3);
    const uint32_t b_kb  = ((lane >> 3) & 1) << 4;
    const int r0 = wm + (lane >> 2);

    CP_WAIT(1);                         // A0 complete (A1 may be in flight)
    __syncthreads();                    // A0 + B visible

    // ---- hoist all B fragments (loop-invariant; 8 ks x 2 ldmx4) ----
    uint32_t bfr[8][2][4];
    #pragma unroll
    for (int ks = 0; ks < 8; ks++) {
        uint32_t hbase = sb + OFF_B + (uint32_t)((ks >> 2) << 14);
        #pragma unroll
        for (int nt2 = 0; nt2 < 2; nt2++)
            ldmx4(bfr[ks][nt2], hbase + sw128((b_row + nt2 * 16) * 128 + b_kb
                                              + (uint32_t)((ks & 3) * 32)));
    }

    // A-fragment address for (mt, ks)
    #define A_ADDR(abase, mt, ks) \
        ((abase) + (uint32_t)(((ks) >> 2) << 14) \
         + sw128((a_row + (mt) * 16) * 128 + a_kb + (uint32_t)(((ks) & 3) * 32)))

    #pragma unroll 1
    for (int i = 0; i < HPG; i++) {
        const uint32_t abase = sb + OFF_A0 + ((i & 1) << 15);
        float* obase = out + ((size_t)bv * 4096u + (size_t)(hp0 + i) * 128u) * 1024u + e0;

        #pragma unroll
        for (int mt = 0; mt < 4; mt++) {
            float acc[4][4];
            #pragma unroll
            for (int nt = 0; nt < 4; nt++)
                #pragma unroll
                for (int jj = 0; jj < 4; jj++) acc[nt][jj] = 0.f;

            // software-pipelined ks loop: af0/af1 double buffer
            uint32_t af0[4], af1[4];
            ldmx4(af0, A_ADDR(abase, mt, 0));
            #pragma unroll
            for (int ks2 = 0; ks2 < 4; ks2++) {
                const int ks = ks2 * 2;
                ldmx4(af1, A_ADDR(abase, mt, ks + 1));   // prefetch odd
                round4(af0);
                #pragma unroll
                for (int nt = 0; nt < 4; nt++)
                    mma_tf32(acc[nt], af0,
                             bfr[ks][nt >> 1][(nt & 1) * 2],
                             bfr[ks][nt >> 1][(nt & 1) * 2 + 1]);
                if (ks + 2 < 8)
                    ldmx4(af0, A_ADDR(abase, mt, ks + 2));  // prefetch next even
                round4(af1);
                #pragma unroll
                for (int nt = 0; nt < 4; nt++)
                    mma_tf32(acc[nt], af1,
                             bfr[ks + 1][nt >> 1][(nt & 1) * 2],
                             bfr[ks + 1][nt >> 1][(nt & 1) * 2 + 1]);
            }

            int row = r0 + mt * 16;
            #pragma unroll
            for (int nt = 0; nt < 4; nt++) {
                int col = c0 + nt * 8;
                float2 v0 = make_float2(acc[nt][0] + bx[nt], acc[nt][1] + by[nt]);
                float2 v1 = make_float2(acc[nt][2] + bx[nt], acc[nt][3] + by[nt]);
                *(float2*)(obase + (size_t)row * 1024u + col) = v0;
                *(float2*)(obase + (size_t)(row + 8) * 1024u + col) = v1;
            }
        }

        __syncthreads();                // all warps done reading buf(i&1)
        if (i + 2 < HPG) {
            LOAD_A(OFF_A0 + ((i & 1) << 15), hp0 + i + 2);
            CP_COMMIT();
        }
        if (i + 1 < HPG) {
            if (i + 2 < HPG) { CP_WAIT(1); } else { CP_WAIT(0); }
            __syncthreads();            // A(i+1) visible
        }
    }
    #undef LOAD_A
    #undef A_ADDR
}

extern "C" void kernel_launch(void* const* d_in, const int* in_sizes, int n_in,
                              void* d_out, int out_size) {
    const float* x    = (const float*)d_in[0];
    const int*   vars = (const int*)d_in[1];
    const float* pw   = (const float*)d_in[2];
    const float* pb   = (const float*)d_in[3];
    float*       out  = (float*)d_out;

    cudaFuncSetAttribute(gemm, cudaFuncAttributeMaxDynamicSharedMemorySize, SMEM_SZ);
    gemm<<<dim3(8, 8, 32), NTHREADS, SMEM_SZ>>>(x, vars, pw, pb, out);
}

// round 16
// speedup vs baseline: 1.2490x; 1.0760x over previous
#include <cuda_runtime.h>
#include <cstdint>

// FlexGroupedVarPatchEmbed tf32 GEMM — L2-traffic-optimized.
// CTA: M=128 x N=256 (512 threads, 16 warps as 2m x 8n, warp tile m64 x n32).
// Doubling N per CTA halves A-tile L2 re-reads (the measured bottleneck).
// HPG=4 M-tiles, double-buffered cp.async A; B frags hoisted to regs;
// RNA-rounded B at load; +0x1000 bit-round on A fragments. rel_err ~2.9e-4.

#define NTHREADS 512
#define HPG 4

__device__ __forceinline__ uint32_t smem_u32(const void* p) {
    uint32_t a;
    asm("{ .reg .u64 t; cvta.to.shared.u64 t, %1; cvt.u32.u64 %0, t; }" : "=r"(a) : "l"(p));
    return a;
}
__device__ __forceinline__ uint32_t sw128(uint32_t off) { return off ^ ((off >> 3) & 0x70); }

__device__ __forceinline__ void cp16(uint32_t dst, const void* src) {
    asm volatile("cp.async.cg.shared.global [%0], [%1], 16;" :: "r"(dst), "l"(src));
}
#define CP_COMMIT() asm volatile("cp.async.commit_group;" ::: "memory")
#define CP_WAIT(n)  asm volatile("cp.async.wait_group %0;" :: "n"(n) : "memory")

__device__ __forceinline__ void ldmx4(uint32_t* f, uint32_t addr) {
    asm volatile("ldmatrix.sync.aligned.m8n8.x4.shared.b16 {%0,%1,%2,%3}, [%4];"
                 : "=r"(f[0]), "=r"(f[1]), "=r"(f[2]), "=r"(f[3]) : "r"(addr));
}
__device__ __forceinline__ void mma_tf32(float* c, const uint32_t* a, uint32_t b0, uint32_t b1) {
    asm volatile(
        "mma.sync.aligned.m16n8k8.row.col.f32.tf32.tf32.f32 "
        "{%0,%1,%2,%3}, {%4,%5,%6,%7}, {%8,%9}, {%0,%1,%2,%3};"
        : "+f"(c[0]), "+f"(c[1]), "+f"(c[2]), "+f"(c[3])
        : "r"(a[0]), "r"(a[1]), "r"(a[2]), "r"(a[3]), "r"(b0), "r"(b1));
}
__device__ __forceinline__ uint32_t rna(float f) {
    uint32_t r;
    asm("cvt.rna.tf32.f32 %0, %1;" : "=r"(r) : "f"(f));
    return r;
}
__device__ __forceinline__ void round4(uint32_t* a) {
    a[0] += 0x1000u; a[1] += 0x1000u; a[2] += 0x1000u; a[3] += 0x1000u;
}

// smem: B 64KB (two 32KB k-halves, 256 rows x 128B) | A buf0 32KB | A buf1 32KB
#define OFF_B   0
#define OFF_A0  65536
#define SMEM_SZ 131072

__global__ __launch_bounds__(NTHREADS, 1)
void gemm(const float* __restrict__ x,
          const int* __restrict__ vars,
          const float* __restrict__ pw,
          const float* __restrict__ pb,
          float* __restrict__ out) {
    extern __shared__ char smem[];
    const uint32_t sb = smem_u32(smem);
    const int tid  = threadIdx.x;
    const int lane = tid & 31;
    const int wid  = tid >> 5;

    const int e0  = blockIdx.x << 8;    // 256-wide E tile
    const int hp0 = blockIdx.y * HPG;
    const int bv  = blockIdx.z;
    const int v   = bv & 15;
    const int var = vars[v];

    const float* xb = x + (size_t)bv * (512u * 512u);

    // ---- A tile loader: patchify x directly (2048 cp16 over 512 threads) ----
    #define LOAD_A(bufbyte, hp) do {                                              \
        const float* _xr = xb + (size_t)(hp) * (16u * 512u);                      \
        _Pragma("unroll")                                                         \
        for (int _j = 0; _j < 4; _j++) {                                          \
            int _idx = tid + _j * 512;                                            \
            int _m = _idx >> 4, _p = (_idx >> 1) & 7, _h = _idx & 1;              \
            const float* _s = _xr + (size_t)(((_m >> 6) << 3) + _p) * 512u        \
                              + ((_m & 63) << 3) + (_h << 2);                     \
            uint32_t _d = sb + (bufbyte) + (uint32_t)((_p >> 2) << 14)            \
                        + sw128((uint32_t)(_m * 128 + (_p & 3) * 32 + _h * 16));  \
            cp16(_d, _s);                                                         \
        }                                                                         \
    } while (0)

    LOAD_A(OFF_A0, hp0);
    CP_COMMIT();                        // G0: A0

    // ---- B tile: gather 256 W[var] rows, RNA-round, STS (one-time) ----
    {
        const float* wb = pw + ((size_t)var * 1024u + e0) * 64u;
        #pragma unroll
        for (int j = 0; j < 8; j++) {
            int idx = tid + j * 512;        // n*16 + c, 4096 total
            int n  = idx >> 4;              // 0..255
            int c  = idx & 15;
            int kh = c >> 3, cc = c & 7;
            float4 w = *(const float4*)(wb + (size_t)n * 64u + kh * 32 + cc * 4);
            uint4 t;
            t.x = rna(w.x); t.y = rna(w.y); t.z = rna(w.z); t.w = rna(w.w);
            uint32_t off = (uint32_t)(kh << 15) + sw128((uint32_t)(n * 128 + cc * 16));
            *(uint4*)(smem + OFF_B + off) = t;
        }
    }

    LOAD_A(OFF_A0 + 32768, hp0 + 1);
    CP_COMMIT();                        // G1: A1

    // ---- warp layout & bias ----
    const int wm = (wid & 1) << 6;      // 0 / 64
    const int wn = (wid >> 1) << 5;     // 0..224 step 32
    const int c0 = wn + ((lane & 3) << 1);
    float bx[4], by[4];
    {
        const float* bias = pb + (size_t)var * 1024u + e0;
        #pragma unroll
        for (int nt = 0; nt < 4; nt++) {
            bx[nt] = bias[c0 + nt * 8];
            by[nt] = bias[c0 + nt * 8 + 1];
        }
    }

    const uint32_t a_row = wm + (lane & 15);
    const uint32_t a_kb  = (lane >> 4) << 4;
    const uint32_t b_row = wn + (lane & 7) + ((lane >> 4) << 3);
    const uint32_t b_kb  = ((lane >> 3) & 1) << 4;
    const int r0 = wm + (lane >> 2);

    CP_WAIT(1);                         // A0 complete (A1 in flight)
    __syncthreads();                    // A0 + B visible

    // ---- hoist all B fragments (loop-invariant; 8 ks x 2 ldmx4) ----
    uint32_t bfr[8][2][4];
    #pragma unroll
    for (int ks = 0; ks < 8; ks++) {
        uint32_t hbase = sb + OFF_B + (uint32_t)((ks >> 2) << 15);
        #pragma unroll
        for (int nt2 = 0; nt2 < 2; nt2++)
            ldmx4(bfr[ks][nt2], hbase + sw128((b_row + nt2 * 16) * 128 + b_kb
                                              + (uint32_t)((ks & 3) * 32)));
    }

    #define A_ADDR(abase, mt, ks) \
        ((abase) + (uint32_t)(((ks) >> 2) << 14) \
         + sw128((a_row + (mt) * 16) * 128 + a_kb + (uint32_t)(((ks) & 3) * 32)))

    #pragma unroll 1
    for (int i = 0; i < HPG; i++) {
        const uint32_t abase = sb + OFF_A0 + ((i & 1) << 15);
        float* obase = out + ((size_t)bv * 4096u + (size_t)(hp0 + i) * 128u) * 1024u + e0;

        #pragma unroll
        for (int mt = 0; mt < 4; mt++) {
            float acc[4][4];
            #pragma unroll
            for (int nt = 0; nt < 4; nt++)
                #pragma unroll
                for (int jj = 0; jj < 4; jj++) acc[nt][jj] = 0.f;

            uint32_t af0[4], af1[4];
            ldmx4(af0, A_ADDR(abase, mt, 0));
            #pragma unroll
            for (int ks2 = 0; ks2 < 4; ks2++) {
                const int ks = ks2 * 2;
                ldmx4(af1, A_ADDR(abase, mt, ks + 1));
                round4(af0);
                #pragma unroll
                for (int nt = 0; nt < 4; nt++)
                    mma_tf32(acc[nt], af0,
                             bfr[ks][nt >> 1][(nt & 1) * 2],
                             bfr[ks][nt >> 1][(nt & 1) * 2 + 1]);
                if (ks + 2 < 8)
                    ldmx4(af0, A_ADDR(abase, mt, ks + 2));
                round4(af1);
                #pragma unroll
                for (int nt = 0; nt < 4; nt++)
                    mma_tf32(acc[nt], af1,
                             bfr[ks + 1][nt >> 1][(nt & 1) * 2],
                             bfr[ks + 1][nt >> 1][(nt & 1) * 2 + 1]);
            }

            int row = r0 + mt * 16;
            #pragma unroll
            for (int nt = 0; nt < 4; nt++) {
                int col = c0 + nt * 8;
                float2 v0 = make_float2(acc[nt][0] + bx[nt], acc[nt][1] + by[nt]);
                float2 v1 = make_float2(acc[nt][2] + bx[nt], acc[nt][3] + by[nt]);
                *(float2*)(obase + (size_t)row * 1024u + col) = v0;
                *(float2*)(obase + (size_t)(row + 8) * 1024u + col) = v1;
            }
        }

        __syncthreads();                // all warps done reading buf(i&1)
        if (i + 2 < HPG) {
            LOAD_A(OFF_A0 + ((i & 1) << 15), hp0 + i + 2);
            CP_COMMIT();
        }
        if (i + 1 < HPG) {
            if (i + 2 < HPG) { CP_WAIT(1); } else { CP_WAIT(0); }
            __syncthreads();            // A(i+1) visible
        }
    }
    #undef LOAD_A
    #undef A_ADDR
}

extern "C" void kernel_launch(void* const* d_in, const int* in_sizes, int n_in,
                              void* d_out, int out_size) {
    const float* x    = (const float*)d_in[0];
    const int*   vars = (const int*)d_in[1];
    const float* pw   = (const float*)d_in[2];
    const float* pb   = (const float*)d_in[3];
    float*       out  = (float*)d_out;

    cudaFuncSetAttribute(gemm, cudaFuncAttributeMaxDynamicSharedMemorySize, SMEM_SZ);
    gemm<<<dim3(4, 8, 32), NTHREADS, SMEM_SZ>>>(x, vars, pw, pb, out);
}